// round 12
// baseline (speedup 1.0000x reference)
#include <cuda_runtime.h>
#include <cuda_fp16.h>
#include <math.h>

#define N_HEADS   8
#define N_LEVELS  3
#define N_POINTS  4
#define D_MODEL   128
#define D_HEAD    16
#define LQ        6400

#define H0 128
#define W0 128
#define H1 64
#define W1 64
#define H2 32
#define W2 32
#define HW0 (H0*W0)
#define HW1 (H1*W1)
#define HW2 (H2*W2)

// scratch — projected features stored in fp16 (halves gather traffic)
__device__ __half g_proj0[HW0 * 128];
__device__ __half g_proj1[HW1 * 128];
__device__ __half g_proj2[HW2 * 128];
__device__ float g_wofft[128 * 192];   // WoffT[c][j]
__device__ float g_woutt[128 * 128];   // WoutT[c][o]
__device__ float g_wk0t[128 * 128];    // Wk0T[c][o]
__device__ float g_wk1t[128 * 128];
__device__ float g_wk2t[64 * 128];
__device__ float g_loc[LQ * 192];      // sampling locations per (q, j)
__device__ uint4 g_lut[96];            // per-sample: {ptr_lo, ptr_hi, W|H<<16, h*3+l}
__device__ int   g_gate;               // producer->consumer gate inside prep

#define N_PRODUCERS 64

typedef unsigned long long ull;

// ---------------------------------------------------------------------------
// packed f32x2 helpers
// ---------------------------------------------------------------------------
__device__ __forceinline__ void ffma2(ull& acc, ull a, ull b) {
    asm("fma.rn.f32x2 %0, %1, %2, %0;" : "+l"(acc) : "l"(a), "l"(b));
}
__device__ __forceinline__ ull bcast2(float w) {
    unsigned int wb = __float_as_uint(w);
    return ((ull)wb << 32) | wb;
}
__device__ __forceinline__ float lo2(ull v) { return __uint_as_float((unsigned int)v); }
__device__ __forceinline__ float hi2(ull v) { return __uint_as_float((unsigned int)(v >> 32)); }

// consumer gate: doubles as the post-load __syncthreads()
__device__ __forceinline__ void gate_sync() {
    if (threadIdx.x == 0) {
        while (*((volatile int*)&g_gate) < N_PRODUCERS)
            __nanosleep(400);
        __threadfence();
    }
    __syncthreads();
}

// ---------------------------------------------------------------------------
// shared transpose block helper (32x32 tile, 128 threads)
// ---------------------------------------------------------------------------
__device__ void transpose_tile(const float* __restrict__ in, float* __restrict__ out,
                               int rows, int cols, int t, float* tile) {
    const int tpr = cols / 32;
    const int by = (t / tpr) * 32, bx = (t % tpr) * 32;
    const int tx = threadIdx.x & 31;
    const int ty0 = threadIdx.x >> 5;
    const int x = bx + tx;
#pragma unroll
    for (int dy = ty0; dy < 32; dy += 4) {
        int y = by + dy;
        if (y < rows && x < cols) tile[dy * 33 + tx] = in[y * cols + x];
    }
    __syncthreads();
    const int xo = by + tx;
#pragma unroll
    for (int dy = ty0; dy < 32; dy += 4) {
        int yo = bx + dy;
        if (yo < cols && xo < rows) out[yo * rows + xo] = tile[tx * 33 + dy];
    }
}

// ---------------------------------------------------------------------------
// prep building blocks (128 threads each) — LDS.64 / ull inner loops
// ---------------------------------------------------------------------------
template <int C>
__device__ void proj_block(const float* __restrict__ feat,
                           const float* __restrict__ WkT,   // [C][128]
                           __half* __restrict__ out, int HW, int blk,
                           float* s) {
    constexpr int PIX = 32;
    const int base = blk * PIX;
    const int tid = threadIdx.x;

    for (int i = tid; i < C * PIX; i += 128) {
        int c = i >> 5, px = i & 31;
        s[i] = feat[c * HW + base + px];
    }
    gate_sync();   // wait for weight transposes (hidden under tile load)

    ull acc[PIX / 2];
#pragma unroll
    for (int v = 0; v < PIX / 2; v++) acc[v] = 0ULL;

    const float* wcol = WkT + tid;   // lanes consecutive -> coalesced
#pragma unroll 4
    for (int c = 0; c < C; c++) {
        ull ww = bcast2(__ldg(wcol + c * 128));
        const ull* s2 = reinterpret_cast<const ull*>(&s[c * PIX]);
#pragma unroll
        for (int v = 0; v < PIX / 2; v++)
            ffma2(acc[v], ww, s2[v]);
    }
#pragma unroll
    for (int v = 0; v < PIX / 2; v++) {
        out[(base + 2 * v) * 128 + tid]     = __float2half_rn(lo2(acc[v]));
        out[(base + 2 * v + 1) * 128 + tid] = __float2half_rn(hi2(acc[v]));
    }
}

#define LOC_STRIDE 18   // padded q-stride: even (ull-aligned), 2-way banks
__device__ void loc_block(int b,
                          const float* __restrict__ query,
                          const float* __restrict__ refp,
                          const float* __restrict__ boff,
                          float* s /* >= 2496 floats */) {
    const int qb = b * 16;
    const int tid = threadIdx.x;
    // s[0 .. 128*18): q tile [c][16 (pad 18)] ; s[2304 .. 2400): ref [16][6]
    for (int i = tid; i < 16 * 128; i += 128) {
        int q = i >> 7, c = i & 127;
        s[c * LOC_STRIDE + q] = query[(qb + q) * 128 + c];
    }
    if (tid < 96) s[2304 + tid] = refp[qb * 6 + tid];
    gate_sync();   // wait for Woff transpose (hidden under tile load)

#pragma unroll
    for (int k = 0; k < 3; k++) {
        const int t = k * 128 + tid;      // 0..383
        const int j = t % 192;
        const int qh = t / 192;
        const int xy = j & 1;
        const int l = (j >> 3) % 3;
        const float scale = 1.f / (float)(128 >> l);

        ull acc[4] = {0, 0, 0, 0};
        const float* wcol = g_wofft + j;
#pragma unroll 4
        for (int c = 0; c < 128; c++) {
            ull w = bcast2(__ldg(wcol + c * 192));
            const ull* s2 = reinterpret_cast<const ull*>(&s[c * LOC_STRIDE + qh * 8]);
#pragma unroll
            for (int v = 0; v < 4; v++)
                ffma2(acc[v], w, s2[v]);
        }
        const float bo = __ldg(boff + j);
#pragma unroll
        for (int v = 0; v < 4; v++) {
            const int q0 = qh * 8 + 2 * v, q1 = q0 + 1;
            const float r0 = s[2304 + q0 * 6 + l * 2 + xy];
            const float r1 = s[2304 + q1 * 6 + l * 2 + xy];
            g_loc[(qb + q0) * 192 + j] = r0 + (lo2(acc[v]) + bo) * scale;
            g_loc[(qb + q1) * 192 + j] = r1 + (hi2(acc[v]) + bo) * scale;
        }
    }
}

// prep: 64 producers (weight transposes) + 16 WoutT + 1 LUT
//       + 400 loc + 512 p0 + 128 p1 + 32 p2   = 1153 blocks
__global__ __launch_bounds__(128)
void prep_kernel(const float* __restrict__ feat0,
                 const float* __restrict__ feat1,
                 const float* __restrict__ feat2,
                 const float* __restrict__ query,
                 const float* __restrict__ refp,
                 const float* __restrict__ boff,
                 const float* __restrict__ Woff,
                 const float* __restrict__ Wout,
                 const float* __restrict__ Wk0,
                 const float* __restrict__ Wk1,
                 const float* __restrict__ Wk2) {
    __shared__ float s[128 * 32];
    const int b = blockIdx.x;
    if (b < N_PRODUCERS) {
        // producers: transposes consumed by this same launch
        if (b < 24)      transpose_tile(Woff, g_wofft, 192, 128, b, s);
        else if (b < 40) transpose_tile(Wk0,  g_wk0t,  128, 128, b - 24, s);
        else if (b < 56) transpose_tile(Wk1,  g_wk1t,  128, 128, b - 40, s);
        else             transpose_tile(Wk2,  g_wk2t,  128, 64,  b - 56, s);
        __threadfence();
        __syncthreads();
        if (threadIdx.x == 0) atomicAdd(&g_gate, 1);
    } else if (b < 80) {
        // Wout transpose: consumed only by main (next launch) — no gate
        transpose_tile(Wout, g_woutt, 128, 128, b - 64, s);
    } else if (b == 80) {
        const int t = threadIdx.x;
        if (t < 96) {
            int h = t / 12, lp = t % 12, l = lp >> 2;
            const __half* base = (l == 0) ? g_proj0 : (l == 1) ? g_proj1 : g_proj2;
            ull p = (ull)(base + h * D_HEAD);
            int Wl = 128 >> l;
            g_lut[t] = make_uint4((unsigned)p, (unsigned)(p >> 32),
                                  (unsigned)(Wl | (Wl << 16)), (unsigned)(h * 3 + l));
        }
    } else if (b < 481) {
        loc_block(b - 81, query, refp, boff, s);
    } else if (b < 993) {
        proj_block<128>(feat0, g_wk0t, g_proj0, HW0, b - 481, s);
    } else if (b < 1121) {
        proj_block<128>(feat1, g_wk1t, g_proj1, HW1, b - 993, s);
    } else {
        proj_block<64>(feat2, g_wk2t, g_proj2, HW2, b - 1121, s);
    }
}
#define PREP_BLOCKS 1153

// ---------------------------------------------------------------------------
// Fused attention kernel. QB=4 queries / block, 256 threads. Includes output
// projection (phase F) — WoutT reads hide under gather latency slack.
// ---------------------------------------------------------------------------
#define QB 4
#define THREADS 256
#define NSAMP (N_HEADS * N_LEVELS * N_POINTS)   // 96
#define LPP   (N_LEVELS * N_POINTS)             // 12
#define HT_STRIDE 6   // 128*6 = 768 = LOC size; even -> ull-aligned; 2-way banks

#define SM_QS    0
#define SM_LOC   (SM_QS + QB*128)            // 512
#define SM_HT    SM_LOC                      // alias (LOC dead after C) 768
#define SM_KS    (SM_LOC + QB*192)           // 1280
#define SM_PF    SM_KS                       // alias (KS dead after E) 512
#define SM_LG    (SM_KS + QB*NSAMP*16)       // 7424
#define SM_QBK   (SM_LG + QB*NSAMP)          // 7808
#define SM_TOTAL (SM_QBK + QB*24)            // 7904
#define SMEM_BYTES (SM_TOTAL * sizeof(float))

__global__ __launch_bounds__(THREADS)
void msda_main_kernel(const float* __restrict__ query,
                      const float* __restrict__ bk0,
                      const float* __restrict__ bk1,
                      const float* __restrict__ bk2,
                      const float* __restrict__ WoutT,
                      const float* __restrict__ bout,
                      float* __restrict__ out) {
    extern __shared__ float sm[];
    const int tid = threadIdx.x;
    const int qbase = blockIdx.x * QB;

    // reset the prep gate for the next graph replay (main is stream-ordered
    // after prep; next replay's prep is stream-ordered after this kernel)
    if (blockIdx.x == 0 && tid == 0) g_gate = 0;

    // ---- Phase A: vectorized loads ------------------------------------------
    {
        const float4* qsrc = reinterpret_cast<const float4*>(query + qbase * 128);
        const float4* lsrc = reinterpret_cast<const float4*>(g_loc + qbase * 192);
        float4* qdst = reinterpret_cast<float4*>(&sm[SM_QS]);
        float4* ldst = reinterpret_cast<float4*>(&sm[SM_LOC]);
        for (int i = tid; i < 320; i += THREADS) {
            if (i < 128) qdst[i] = qsrc[i];
            else         ldst[i - 128] = lsrc[i - 128];
        }
    }
    __syncthreads();

    // ---- Phase A2: qbk[q][h][l] = q_h . bk_l_h -------------------------------
    if (tid < QB * 24) {
        const int q = tid / 24;
        const int r = tid % 24;
        const int h = r / 3;
        const int l = r % 3;
        const float* bk = (l == 0) ? bk0 : (l == 1) ? bk1 : bk2;
        const float* qp = &sm[SM_QS + q * 128 + h * D_HEAD];
        float a = 0.f;
#pragma unroll
        for (int d = 0; d < D_HEAD; d++)
            a += qp[d] * __ldg(bk + h * D_HEAD + d);
        sm[SM_QBK + tid] = a;
    }
    __syncthreads();

    // ---- Phase C: quad-cooperative bilinear gather (fp16 feats) + logits -----
#pragma unroll
    for (int it = 0; it < 6; it++) {
        const int i = it * THREADS + tid;
        const int q = i / 384;
        const int r = i - q * 384;
        const int s = r >> 2;
        const int d4 = r & 3;

        const uint4 e = __ldg(&g_lut[s]);
        const __half* projc = (const __half*)(((ull)e.y << 32) | (ull)e.x);
        const int Wl = (int)(e.z & 0xffffu);
        const int Hl = (int)(e.z >> 16);

        const float locx = sm[SM_LOC + q * 192 + s * 2];
        const float locy = sm[SM_LOC + q * 192 + s * 2 + 1];

        const float x = locx * (float)Wl - 0.5f;
        const float y = locy * (float)Hl - 0.5f;
        const float xf = floorf(x), yf = floorf(y);
        const int x0 = (int)xf, y0 = (int)yf;
        const float wx = x - xf, wy = y - yf;

        float wgt[4];
        const uint2* addr[4];
#pragma unroll
        for (int t = 0; t < 4; t++) {
            const int xi = x0 + (t & 1);
            const int yi = y0 + (t >> 1);
            const bool valid = (xi >= 0) & (xi < Wl) & (yi >= 0) & (yi < Hl);
            const float w = ((t & 1) ? wx : (1.f - wx)) * ((t >> 1) ? wy : (1.f - wy));
            wgt[t] = valid ? w : 0.f;
            const int xic = min(max(xi, 0), Wl - 1);
            const int yic = min(max(yi, 0), Hl - 1);
            addr[t] = reinterpret_cast<const uint2*>(projc + (yic * Wl + xic) * 128) + d4;
        }
        uint2 u0 = __ldg(addr[0]);
        uint2 u1 = __ldg(addr[1]);
        uint2 u2 = __ldg(addr[2]);
        uint2 u3 = __ldg(addr[3]);

        float2 a0 = __half22float2(*reinterpret_cast<__half2*>(&u0.x));
        float2 b0 = __half22float2(*reinterpret_cast<__half2*>(&u0.y));
        float2 a1 = __half22float2(*reinterpret_cast<__half2*>(&u1.x));
        float2 b1 = __half22float2(*reinterpret_cast<__half2*>(&u1.y));
        float2 a2 = __half22float2(*reinterpret_cast<__half2*>(&u2.x));
        float2 b2 = __half22float2(*reinterpret_cast<__half2*>(&u2.y));
        float2 a3 = __half22float2(*reinterpret_cast<__half2*>(&u3.x));
        float2 b3 = __half22float2(*reinterpret_cast<__half2*>(&u3.y));

        float4 k;
        k.x = wgt[0] * a0.x + wgt[1] * a1.x + wgt[2] * a2.x + wgt[3] * a3.x;
        k.y = wgt[0] * a0.y + wgt[1] * a1.y + wgt[2] * a2.y + wgt[3] * a3.y;
        k.z = wgt[0] * b0.x + wgt[1] * b1.x + wgt[2] * b2.x + wgt[3] * b3.x;
        k.w = wgt[0] * b0.y + wgt[1] * b1.y + wgt[2] * b2.y + wgt[3] * b3.y;

        const int coff = (s / LPP) * D_HEAD + d4 * 4;
        const float4 qv = *reinterpret_cast<const float4*>(&sm[SM_QS + q * 128 + coff]);
        float part = qv.x * k.x + qv.y * k.y + qv.z * k.z + qv.w * k.w;
        part += __shfl_xor_sync(0xffffffffu, part, 1);
        part += __shfl_xor_sync(0xffffffffu, part, 2);

        *reinterpret_cast<float4*>(&sm[SM_KS + (q * NSAMP + s) * D_HEAD + d4 * 4]) = k;
        if (d4 == 0)
            sm[SM_LG + q * NSAMP + s] = part + sm[SM_QBK + q * 24 + e.w];
    }
    __syncthreads();

    // ---- Phase D: softmax per (q, h) over 12 ---------------------------------
    if (tid < QB * N_HEADS) {
        const int q = tid / N_HEADS, h = tid % N_HEADS;
        float* lrow = &sm[SM_LG + q * NSAMP + h * LPP];
        float m = -1e30f;
#pragma unroll
        for (int t = 0; t < LPP; t++) m = fmaxf(m, 0.25f * lrow[t]);
        float ssum = 0.f;
#pragma unroll
        for (int t = 0; t < LPP; t++) {
            float e = __expf(0.25f * lrow[t] - m);
            lrow[t] = e;
            ssum += e;
        }
        float inv = 1.f / ssum;
#pragma unroll
        for (int t = 0; t < LPP; t++) lrow[t] *= inv;
    }
    __syncthreads();

    // ---- Phase E: weighted sum (+ bias via attn level-sums) -> HT [c][q] -----
#pragma unroll
    for (int it = 0; it < 2; it++) {
        const int i = it * THREADS + tid;
        const int q = i >> 7;
        const int hd = i & 127;
        const int h = hd >> 4;
        const int d = hd & 15;
        const float* attn = &sm[SM_LG + q * NSAMP + h * LPP];
        const float* kk = &sm[SM_KS + (q * NSAMP + h * LPP) * D_HEAD + d];
        float a = 0.f;
        float w0 = 0.f, w1 = 0.f, w2 = 0.f;
#pragma unroll
        for (int lp = 0; lp < LPP; lp++) {
            const float at = attn[lp];
            a += at * kk[lp * D_HEAD];
            if (lp < 4) w0 += at;
            else if (lp < 8) w1 += at;
            else w2 += at;
        }
        a += w0 * __ldg(bk0 + hd) + w1 * __ldg(bk1 + hd) + w2 * __ldg(bk2 + hd);
        sm[SM_HT + hd * HT_STRIDE + q] = a;
    }
    __syncthreads();

    // ---- Phase F: out[q][o] = hs[q] . WoutT[:,o] + b, c-split over 2 halves --
    {
        const int o = tid & 127;
        const int chalf = tid >> 7;
        const int cbase = chalf * 64;
        ull acc[2] = {0, 0};
        const float* wt = WoutT + o;
#pragma unroll 4
        for (int c = 0; c < 64; c++) {
            const int cc = cbase + c;
            ull ww = bcast2(__ldg(wt + cc * 128));
            const ull* hp = reinterpret_cast<const ull*>(&sm[SM_HT + cc * HT_STRIDE]);
            ffma2(acc[0], ww, hp[0]);
            ffma2(acc[1], ww, hp[1]);
        }
        if (chalf == 1) {
            ull* pf = reinterpret_cast<ull*>(&sm[SM_PF]);
            pf[o * 2]     = acc[0];
            pf[o * 2 + 1] = acc[1];
        }
        __syncthreads();
        if (chalf == 0) {
            const float* pf = &sm[SM_PF + o * 4];
            const float b = __ldg(bout + o);
            out[(qbase + 0) * 128 + o] = lo2(acc[0]) + pf[0] + b;
            out[(qbase + 1) * 128 + o] = hi2(acc[0]) + pf[1] + b;
            out[(qbase + 2) * 128 + o] = lo2(acc[1]) + pf[2] + b;
            out[(qbase + 3) * 128 + o] = hi2(acc[1]) + pf[3] + b;
        }
    }
}

// ---------------------------------------------------------------------------
// Launch
// ---------------------------------------------------------------------------
extern "C" void kernel_launch(void* const* d_in, const int* in_sizes, int n_in,
                              void* d_out, int out_size) {
    const float* query = (const float*)d_in[0];
    const float* refp  = (const float*)d_in[1];
    const float* feat0 = (const float*)d_in[2];
    const float* feat1 = (const float*)d_in[3];
    const float* feat2 = (const float*)d_in[4];
    const float* Woff  = (const float*)d_in[6];
    const float* boff  = (const float*)d_in[7];
    const float* Wk0   = (const float*)d_in[8];
    const float* bk0   = (const float*)d_in[9];
    const float* Wk1   = (const float*)d_in[10];
    const float* bk1   = (const float*)d_in[11];
    const float* Wk2   = (const float*)d_in[12];
    const float* bk2   = (const float*)d_in[13];
    const float* Wout  = (const float*)d_in[14];
    const float* bout  = (const float*)d_in[15];
    float* out = (float*)d_out;

    float* woutt;
    cudaGetSymbolAddress((void**)&woutt, g_woutt);

    static bool attr_set = false;
    if (!attr_set) {
        cudaFuncSetAttribute(msda_main_kernel,
                             cudaFuncAttributeMaxDynamicSharedMemorySize,
                             (int)SMEM_BYTES);
        attr_set = true;
    }

    prep_kernel<<<PREP_BLOCKS, 128>>>(feat0, feat1, feat2, query, refp, boff,
                                      Woff, Wout, Wk0, Wk1, Wk2);
    msda_main_kernel<<<LQ / QB, THREADS, SMEM_BYTES>>>(
        query, bk0, bk1, bk2, woutt, bout, out);
}

// round 13
// speedup vs baseline: 1.0230x; 1.0230x over previous
#include <cuda_runtime.h>
#include <cuda_fp16.h>
#include <math.h>

#define N_HEADS   8
#define N_LEVELS  3
#define N_POINTS  4
#define D_MODEL   128
#define D_HEAD    16
#define LQ        6400

#define H0 128
#define W0 128
#define H1 64
#define W1 64
#define H2 32
#define W2 32
#define HW0 (H0*W0)
#define HW1 (H1*W1)
#define HW2 (H2*W2)

// scratch — projected features stored in fp16 (halves gather traffic)
__device__ __half g_proj0[HW0 * 128];
__device__ __half g_proj1[HW1 * 128];
__device__ __half g_proj2[HW2 * 128];
__device__ float g_wofft[128 * 192];   // WoffT[c][j]
__device__ float g_woutt[128 * 128];   // WoutT[c][o]
__device__ float g_wk0t[128 * 128];    // Wk0T[c][o]
__device__ float g_wk1t[128 * 128];
__device__ float g_wk2t[64 * 128];
__device__ float g_loc[LQ * 192];      // sampling locations per (q, j)
__device__ uint4 g_lut[96];            // per-sample: {ptr_lo, ptr_hi, W|H<<16, h*3+l}
__device__ int   g_gate;               // producer->consumer gate inside prep

#define N_PRODUCERS 64

typedef unsigned long long ull;

// ---------------------------------------------------------------------------
// packed f32x2 helpers
// ---------------------------------------------------------------------------
__device__ __forceinline__ void ffma2(ull& acc, ull a, ull b) {
    asm("fma.rn.f32x2 %0, %1, %2, %0;" : "+l"(acc) : "l"(a), "l"(b));
}
__device__ __forceinline__ ull bcast2(float w) {
    unsigned int wb = __float_as_uint(w);
    return ((ull)wb << 32) | wb;
}
__device__ __forceinline__ float lo2(ull v) { return __uint_as_float((unsigned int)v); }
__device__ __forceinline__ float hi2(ull v) { return __uint_as_float((unsigned int)(v >> 32)); }

// consumer gate: doubles as the post-load __syncthreads()
__device__ __forceinline__ void gate_sync() {
    if (threadIdx.x == 0) {
        while (*((volatile int*)&g_gate) < N_PRODUCERS)
            __nanosleep(400);
        __threadfence();
    }
    __syncthreads();
}

// ---------------------------------------------------------------------------
// shared transpose block helper (32x32 tile, 128 threads)
// ---------------------------------------------------------------------------
__device__ void transpose_tile(const float* __restrict__ in, float* __restrict__ out,
                               int rows, int cols, int t, float* tile) {
    const int tpr = cols / 32;
    const int by = (t / tpr) * 32, bx = (t % tpr) * 32;
    const int tx = threadIdx.x & 31;
    const int ty0 = threadIdx.x >> 5;
    const int x = bx + tx;
#pragma unroll
    for (int dy = ty0; dy < 32; dy += 4) {
        int y = by + dy;
        if (y < rows && x < cols) tile[dy * 33 + tx] = in[y * cols + x];
    }
    __syncthreads();
    const int xo = by + tx;
#pragma unroll
    for (int dy = ty0; dy < 32; dy += 4) {
        int yo = bx + dy;
        if (yo < cols && xo < rows) out[yo * rows + xo] = tile[tx * 33 + dy];
    }
}

// ---------------------------------------------------------------------------
// prep building blocks (128 threads each) — LDS.64 / ull inner loops
// ---------------------------------------------------------------------------
template <int C>
__device__ void proj_block(const float* __restrict__ feat,
                           const float* __restrict__ WkT,   // [C][128]
                           __half* __restrict__ out, int HW, int blk,
                           float* s) {
    constexpr int PIX = 32;
    const int base = blk * PIX;
    const int tid = threadIdx.x;

    for (int i = tid; i < C * PIX; i += 128) {
        int c = i >> 5, px = i & 31;
        s[i] = feat[c * HW + base + px];
    }
    gate_sync();   // wait for weight transposes (hidden under tile load)

    ull acc[PIX / 2];
#pragma unroll
    for (int v = 0; v < PIX / 2; v++) acc[v] = 0ULL;

    const float* wcol = WkT + tid;   // lanes consecutive -> coalesced
#pragma unroll 8
    for (int c = 0; c < C; c++) {
        ull ww = bcast2(__ldg(wcol + c * 128));
        const ull* s2 = reinterpret_cast<const ull*>(&s[c * PIX]);
#pragma unroll
        for (int v = 0; v < PIX / 2; v++)
            ffma2(acc[v], ww, s2[v]);
    }
#pragma unroll
    for (int v = 0; v < PIX / 2; v++) {
        out[(base + 2 * v) * 128 + tid]     = __float2half_rn(lo2(acc[v]));
        out[(base + 2 * v + 1) * 128 + tid] = __float2half_rn(hi2(acc[v]));
    }
}

#define LOC_STRIDE 18   // padded q-stride: even (ull-aligned), 2-way banks
__device__ void loc_block(int b,
                          const float* __restrict__ query,
                          const float* __restrict__ refp,
                          const float* __restrict__ boff,
                          float* s /* >= 2496 floats */) {
    const int qb = b * 16;
    const int tid = threadIdx.x;
    // s[0 .. 128*18): q tile [c][16 (pad 18)] ; s[2304 .. 2400): ref [16][6]
    for (int i = tid; i < 16 * 128; i += 128) {
        int q = i >> 7, c = i & 127;
        s[c * LOC_STRIDE + q] = query[(qb + q) * 128 + c];
    }
    if (tid < 96) s[2304 + tid] = refp[qb * 6 + tid];
    gate_sync();   // wait for Woff transpose (hidden under tile load)

#pragma unroll
    for (int k = 0; k < 3; k++) {
        const int t = k * 128 + tid;      // 0..383
        const int j = t % 192;
        const int qh = t / 192;
        const int xy = j & 1;
        const int l = (j >> 3) % 3;
        const float scale = 1.f / (float)(128 >> l);

        ull acc[4] = {0, 0, 0, 0};
        const float* wcol = g_wofft + j;
#pragma unroll 8
        for (int c = 0; c < 128; c++) {
            ull w = bcast2(__ldg(wcol + c * 192));
            const ull* s2 = reinterpret_cast<const ull*>(&s[c * LOC_STRIDE + qh * 8]);
#pragma unroll
            for (int v = 0; v < 4; v++)
                ffma2(acc[v], w, s2[v]);
        }
        const float bo = __ldg(boff + j);
#pragma unroll
        for (int v = 0; v < 4; v++) {
            const int q0 = qh * 8 + 2 * v, q1 = q0 + 1;
            const float r0 = s[2304 + q0 * 6 + l * 2 + xy];
            const float r1 = s[2304 + q1 * 6 + l * 2 + xy];
            g_loc[(qb + q0) * 192 + j] = r0 + (lo2(acc[v]) + bo) * scale;
            g_loc[(qb + q1) * 192 + j] = r1 + (hi2(acc[v]) + bo) * scale;
        }
    }
}

// prep: 64 producers (weight transposes) + 16 WoutT + 1 LUT
//       + 400 loc + 512 p0 + 128 p1 + 32 p2   = 1153 blocks
__global__ __launch_bounds__(128)
void prep_kernel(const float* __restrict__ feat0,
                 const float* __restrict__ feat1,
                 const float* __restrict__ feat2,
                 const float* __restrict__ query,
                 const float* __restrict__ refp,
                 const float* __restrict__ boff,
                 const float* __restrict__ Woff,
                 const float* __restrict__ Wout,
                 const float* __restrict__ Wk0,
                 const float* __restrict__ Wk1,
                 const float* __restrict__ Wk2) {
    __shared__ float s[128 * 32];
    const int b = blockIdx.x;
    if (b < N_PRODUCERS) {
        // producers: transposes consumed by this same launch
        if (b < 24)      transpose_tile(Woff, g_wofft, 192, 128, b, s);
        else if (b < 40) transpose_tile(Wk0,  g_wk0t,  128, 128, b - 24, s);
        else if (b < 56) transpose_tile(Wk1,  g_wk1t,  128, 128, b - 40, s);
        else             transpose_tile(Wk2,  g_wk2t,  128, 64,  b - 56, s);
        __threadfence();
        __syncthreads();
        if (threadIdx.x == 0) atomicAdd(&g_gate, 1);
    } else if (b < 80) {
        // Wout transpose: consumed only by main (next launch) — no gate
        transpose_tile(Wout, g_woutt, 128, 128, b - 64, s);
    } else if (b == 80) {
        const int t = threadIdx.x;
        if (t < 96) {
            int h = t / 12, lp = t % 12, l = lp >> 2;
            const __half* base = (l == 0) ? g_proj0 : (l == 1) ? g_proj1 : g_proj2;
            ull p = (ull)(base + h * D_HEAD);
            int Wl = 128 >> l;
            g_lut[t] = make_uint4((unsigned)p, (unsigned)(p >> 32),
                                  (unsigned)(Wl | (Wl << 16)), (unsigned)(h * 3 + l));
        }
    } else if (b < 481) {
        loc_block(b - 81, query, refp, boff, s);
    } else if (b < 993) {
        proj_block<128>(feat0, g_wk0t, g_proj0, HW0, b - 481, s);
    } else if (b < 1121) {
        proj_block<128>(feat1, g_wk1t, g_proj1, HW1, b - 993, s);
    } else {
        proj_block<64>(feat2, g_wk2t, g_proj2, HW2, b - 1121, s);
    }
}
#define PREP_BLOCKS 1153

// ---------------------------------------------------------------------------
// Fused attention kernel. QB=4 queries / block, 256 threads. Includes output
// projection (phase F) — WoutT reads hide under gather latency slack.
// ---------------------------------------------------------------------------
#define QB 4
#define THREADS 256
#define NSAMP (N_HEADS * N_LEVELS * N_POINTS)   // 96
#define LPP   (N_LEVELS * N_POINTS)             // 12
#define HT_STRIDE 6   // 128*6 = 768 = LOC size; even -> ull-aligned; 2-way banks

#define SM_QS    0
#define SM_LOC   (SM_QS + QB*128)            // 512
#define SM_HT    SM_LOC                      // alias (LOC dead after C) 768
#define SM_KS    (SM_LOC + QB*192)           // 1280
#define SM_PF    SM_KS                       // alias (KS dead after E) 512
#define SM_LG    (SM_KS + QB*NSAMP*16)       // 7424
#define SM_QBK   (SM_LG + QB*NSAMP)          // 7808
#define SM_TOTAL (SM_QBK + QB*24)            // 7904
#define SMEM_BYTES (SM_TOTAL * sizeof(float))

__global__ __launch_bounds__(THREADS)
void msda_main_kernel(const float* __restrict__ query,
                      const float* __restrict__ bk0,
                      const float* __restrict__ bk1,
                      const float* __restrict__ bk2,
                      const float* __restrict__ WoutT,
                      const float* __restrict__ bout,
                      float* __restrict__ out) {
    extern __shared__ float sm[];
    const int tid = threadIdx.x;
    const int qbase = blockIdx.x * QB;

    // reset the prep gate for the next graph replay (main is stream-ordered
    // after prep; next replay's prep is stream-ordered after this kernel)
    if (blockIdx.x == 0 && tid == 0) g_gate = 0;

    // ---- Phase A: vectorized loads ------------------------------------------
    {
        const float4* qsrc = reinterpret_cast<const float4*>(query + qbase * 128);
        const float4* lsrc = reinterpret_cast<const float4*>(g_loc + qbase * 192);
        float4* qdst = reinterpret_cast<float4*>(&sm[SM_QS]);
        float4* ldst = reinterpret_cast<float4*>(&sm[SM_LOC]);
        for (int i = tid; i < 320; i += THREADS) {
            if (i < 128) qdst[i] = qsrc[i];
            else         ldst[i - 128] = lsrc[i - 128];
        }
    }
    __syncthreads();

    // ---- Phase A2: qbk[q][h][l] = q_h . bk_l_h -------------------------------
    if (tid < QB * 24) {
        const int q = tid / 24;
        const int r = tid % 24;
        const int h = r / 3;
        const int l = r % 3;
        const float* bk = (l == 0) ? bk0 : (l == 1) ? bk1 : bk2;
        const float* qp = &sm[SM_QS + q * 128 + h * D_HEAD];
        float a = 0.f;
#pragma unroll
        for (int d = 0; d < D_HEAD; d++)
            a += qp[d] * __ldg(bk + h * D_HEAD + d);
        sm[SM_QBK + tid] = a;
    }
    __syncthreads();

    // ---- Phase C: quad-cooperative bilinear gather (fp16 feats) + logits -----
#pragma unroll
    for (int it = 0; it < 6; it++) {
        const int i = it * THREADS + tid;
        const int q = i / 384;
        const int r = i - q * 384;
        const int s = r >> 2;
        const int d4 = r & 3;

        const uint4 e = __ldg(&g_lut[s]);
        const __half* projc = (const __half*)(((ull)e.y << 32) | (ull)e.x);
        const int Wl = (int)(e.z & 0xffffu);
        const int Hl = (int)(e.z >> 16);

        const float locx = sm[SM_LOC + q * 192 + s * 2];
        const float locy = sm[SM_LOC + q * 192 + s * 2 + 1];

        const float x = locx * (float)Wl - 0.5f;
        const float y = locy * (float)Hl - 0.5f;
        const float xf = floorf(x), yf = floorf(y);
        const int x0 = (int)xf, y0 = (int)yf;
        const float wx = x - xf, wy = y - yf;

        float wgt[4];
        const uint2* addr[4];
#pragma unroll
        for (int t = 0; t < 4; t++) {
            const int xi = x0 + (t & 1);
            const int yi = y0 + (t >> 1);
            const bool valid = (xi >= 0) & (xi < Wl) & (yi >= 0) & (yi < Hl);
            const float w = ((t & 1) ? wx : (1.f - wx)) * ((t >> 1) ? wy : (1.f - wy));
            wgt[t] = valid ? w : 0.f;
            const int xic = min(max(xi, 0), Wl - 1);
            const int yic = min(max(yi, 0), Hl - 1);
            addr[t] = reinterpret_cast<const uint2*>(projc + (yic * Wl + xic) * 128) + d4;
        }
        uint2 u0 = __ldg(addr[0]);
        uint2 u1 = __ldg(addr[1]);
        uint2 u2 = __ldg(addr[2]);
        uint2 u3 = __ldg(addr[3]);

        float2 a0 = __half22float2(*reinterpret_cast<__half2*>(&u0.x));
        float2 b0 = __half22float2(*reinterpret_cast<__half2*>(&u0.y));
        float2 a1 = __half22float2(*reinterpret_cast<__half2*>(&u1.x));
        float2 b1 = __half22float2(*reinterpret_cast<__half2*>(&u1.y));
        float2 a2 = __half22float2(*reinterpret_cast<__half2*>(&u2.x));
        float2 b2 = __half22float2(*reinterpret_cast<__half2*>(&u2.y));
        float2 a3 = __half22float2(*reinterpret_cast<__half2*>(&u3.x));
        float2 b3 = __half22float2(*reinterpret_cast<__half2*>(&u3.y));

        float4 k;
        k.x = wgt[0] * a0.x + wgt[1] * a1.x + wgt[2] * a2.x + wgt[3] * a3.x;
        k.y = wgt[0] * a0.y + wgt[1] * a1.y + wgt[2] * a2.y + wgt[3] * a3.y;
        k.z = wgt[0] * b0.x + wgt[1] * b1.x + wgt[2] * b2.x + wgt[3] * b3.x;
        k.w = wgt[0] * b0.y + wgt[1] * b1.y + wgt[2] * b2.y + wgt[3] * b3.y;

        const int coff = (s / LPP) * D_HEAD + d4 * 4;
        const float4 qv = *reinterpret_cast<const float4*>(&sm[SM_QS + q * 128 + coff]);
        float part = qv.x * k.x + qv.y * k.y + qv.z * k.z + qv.w * k.w;
        part += __shfl_xor_sync(0xffffffffu, part, 1);
        part += __shfl_xor_sync(0xffffffffu, part, 2);

        *reinterpret_cast<float4*>(&sm[SM_KS + (q * NSAMP + s) * D_HEAD + d4 * 4]) = k;
        if (d4 == 0)
            sm[SM_LG + q * NSAMP + s] = part + sm[SM_QBK + q * 24 + e.w];
    }
    __syncthreads();

    // ---- Phase D: softmax per (q, h) over 12 ---------------------------------
    if (tid < QB * N_HEADS) {
        const int q = tid / N_HEADS, h = tid % N_HEADS;
        float* lrow = &sm[SM_LG + q * NSAMP + h * LPP];
        float m = -1e30f;
#pragma unroll
        for (int t = 0; t < LPP; t++) m = fmaxf(m, 0.25f * lrow[t]);
        float ssum = 0.f;
#pragma unroll
        for (int t = 0; t < LPP; t++) {
            float e = __expf(0.25f * lrow[t] - m);
            lrow[t] = e;
            ssum += e;
        }
        float inv = 1.f / ssum;
#pragma unroll
        for (int t = 0; t < LPP; t++) lrow[t] *= inv;
    }
    __syncthreads();

    // ---- Phase E: weighted sum (+ bias via attn level-sums) -> HT [c][q] -----
#pragma unroll
    for (int it = 0; it < 2; it++) {
        const int i = it * THREADS + tid;
        const int q = i >> 7;
        const int hd = i & 127;
        const int h = hd >> 4;
        const int d = hd & 15;
        const float* attn = &sm[SM_LG + q * NSAMP + h * LPP];
        const float* kk = &sm[SM_KS + (q * NSAMP + h * LPP) * D_HEAD + d];
        float a = 0.f;
        float w0 = 0.f, w1 = 0.f, w2 = 0.f;
#pragma unroll
        for (int lp = 0; lp < LPP; lp++) {
            const float at = attn[lp];
            a += at * kk[lp * D_HEAD];
            if (lp < 4) w0 += at;
            else if (lp < 8) w1 += at;
            else w2 += at;
        }
        a += w0 * __ldg(bk0 + hd) + w1 * __ldg(bk1 + hd) + w2 * __ldg(bk2 + hd);
        sm[SM_HT + hd * HT_STRIDE + q] = a;
    }
    __syncthreads();

    // ---- Phase F: out[q][o] = hs[q] . WoutT[:,o] + b, c-split over 2 halves --
    {
        const int o = tid & 127;
        const int chalf = tid >> 7;
        const int cbase = chalf * 64;
        ull acc[2] = {0, 0};
        const float* wt = WoutT + o;
#pragma unroll 4
        for (int c = 0; c < 64; c++) {
            const int cc = cbase + c;
            ull ww = bcast2(__ldg(wt + cc * 128));
            const ull* hp = reinterpret_cast<const ull*>(&sm[SM_HT + cc * HT_STRIDE]);
            ffma2(acc[0], ww, hp[0]);
            ffma2(acc[1], ww, hp[1]);
        }
        if (chalf == 1) {
            ull* pf = reinterpret_cast<ull*>(&sm[SM_PF]);
            pf[o * 2]     = acc[0];
            pf[o * 2 + 1] = acc[1];
        }
        __syncthreads();
        if (chalf == 0) {
            const float* pf = &sm[SM_PF + o * 4];
            const float b = __ldg(bout + o);
            out[(qbase + 0) * 128 + o] = lo2(acc[0]) + pf[0] + b;
            out[(qbase + 1) * 128 + o] = hi2(acc[0]) + pf[1] + b;
            out[(qbase + 2) * 128 + o] = lo2(acc[1]) + pf[2] + b;
            out[(qbase + 3) * 128 + o] = hi2(acc[1]) + pf[3] + b;
        }
    }
}

// ---------------------------------------------------------------------------
// Launch
// ---------------------------------------------------------------------------
extern "C" void kernel_launch(void* const* d_in, const int* in_sizes, int n_in,
                              void* d_out, int out_size) {
    const float* query = (const float*)d_in[0];
    const float* refp  = (const float*)d_in[1];
    const float* feat0 = (const float*)d_in[2];
    const float* feat1 = (const float*)d_in[3];
    const float* feat2 = (const float*)d_in[4];
    const float* Woff  = (const float*)d_in[6];
    const float* boff  = (const float*)d_in[7];
    const float* Wk0   = (const float*)d_in[8];
    const float* bk0   = (const float*)d_in[9];
    const float* Wk1   = (const float*)d_in[10];
    const float* bk1   = (const float*)d_in[11];
    const float* Wk2   = (const float*)d_in[12];
    const float* bk2   = (const float*)d_in[13];
    const float* Wout  = (const float*)d_in[14];
    const float* bout  = (const float*)d_in[15];
    float* out = (float*)d_out;

    float* woutt;
    cudaGetSymbolAddress((void**)&woutt, g_woutt);

    static bool attr_set = false;
    if (!attr_set) {
        cudaFuncSetAttribute(msda_main_kernel,
                             cudaFuncAttributeMaxDynamicSharedMemorySize,
                             (int)SMEM_BYTES);
        // cap prep's smem carveout at ~50% so its weight streams stay
        // L1-resident (14 blocks x 16KB was eating the entire L1D)
        cudaFuncSetAttribute(prep_kernel,
                             cudaFuncAttributePreferredSharedMemoryCarveout, 50);
        attr_set = true;
    }

    prep_kernel<<<PREP_BLOCKS, 128>>>(feat0, feat1, feat2, query, refp, boff,
                                      Woff, Wout, Wk0, Wk1, Wk2);
    msda_main_kernel<<<LQ / QB, THREADS, SMEM_BYTES>>>(
        query, bk0, bk1, bk2, woutt, bout, out);
}

// round 14
// speedup vs baseline: 1.0268x; 1.0038x over previous
#include <cuda_runtime.h>
#include <cuda_fp16.h>
#include <math.h>

#define N_HEADS   8
#define N_LEVELS  3
#define N_POINTS  4
#define D_MODEL   128
#define D_HEAD    16
#define LQ        6400

#define H0 128
#define W0 128
#define H1 64
#define W1 64
#define H2 32
#define W2 32
#define HW0 (H0*W0)
#define HW1 (H1*W1)
#define HW2 (H2*W2)

// scratch — projected features stored in fp16 (halves gather traffic)
__device__ __half g_proj0[HW0 * 128];
__device__ __half g_proj1[HW1 * 128];
__device__ __half g_proj2[HW2 * 128];
__device__ float g_wofft[128 * 192];   // WoffT[c][j]
__device__ float g_woutt[128 * 128];   // WoutT[c][o]
__device__ float g_wk0t[128 * 128];    // Wk0T[c][o]
__device__ float g_wk1t[128 * 128];
__device__ float g_wk2t[64 * 128];
__device__ float g_loc[LQ * 192];      // sampling locations per (q, j)
__device__ uint4 g_lut[96];            // per-sample: {ptr_lo, ptr_hi, W|H<<16, h*3+l}
__device__ int   g_gate;               // producer->consumer gate inside prep

#define N_PRODUCERS 64

typedef unsigned long long ull;

// ---------------------------------------------------------------------------
// packed f32x2 helpers
// ---------------------------------------------------------------------------
__device__ __forceinline__ void ffma2(ull& acc, ull a, ull b) {
    asm("fma.rn.f32x2 %0, %1, %2, %0;" : "+l"(acc) : "l"(a), "l"(b));
}
__device__ __forceinline__ ull bcast2(float w) {
    unsigned int wb = __float_as_uint(w);
    return ((ull)wb << 32) | wb;
}
__device__ __forceinline__ ull d2u(double d) {
    return (ull)__double_as_longlong(d);   // register-level no-op
}
__device__ __forceinline__ float lo2(ull v) { return __uint_as_float((unsigned int)v); }
__device__ __forceinline__ float hi2(ull v) { return __uint_as_float((unsigned int)(v >> 32)); }

// consumer gate: doubles as the post-load __syncthreads()
__device__ __forceinline__ void gate_sync() {
    if (threadIdx.x == 0) {
        while (*((volatile int*)&g_gate) < N_PRODUCERS)
            __nanosleep(400);
        __threadfence();
    }
    __syncthreads();
}

// ---------------------------------------------------------------------------
// shared transpose block helper (32x32 tile, 128 threads)
// ---------------------------------------------------------------------------
__device__ void transpose_tile(const float* __restrict__ in, float* __restrict__ out,
                               int rows, int cols, int t, float* tile) {
    const int tpr = cols / 32;
    const int by = (t / tpr) * 32, bx = (t % tpr) * 32;
    const int tx = threadIdx.x & 31;
    const int ty0 = threadIdx.x >> 5;
    const int x = bx + tx;
#pragma unroll
    for (int dy = ty0; dy < 32; dy += 4) {
        int y = by + dy;
        if (y < rows && x < cols) tile[dy * 33 + tx] = in[y * cols + x];
    }
    __syncthreads();
    const int xo = by + tx;
#pragma unroll
    for (int dy = ty0; dy < 32; dy += 4) {
        int yo = bx + dy;
        if (yo < cols && xo < rows) out[yo * rows + xo] = tile[tx * 33 + dy];
    }
}

// ---------------------------------------------------------------------------
// prep building blocks (128 threads each)
// inner loops: LDS.128 via double2 (aligned 64-bit pairs, zero MOVs)
// ---------------------------------------------------------------------------
template <int C>
__device__ void proj_block(const float* __restrict__ feat,
                           const float* __restrict__ WkT,   // [C][128]
                           __half* __restrict__ out, int HW, int blk,
                           float* s) {
    constexpr int PIX = 32;
    const int base = blk * PIX;
    const int tid = threadIdx.x;

    for (int i = tid; i < C * PIX; i += 128) {
        int c = i >> 5, px = i & 31;
        s[i] = feat[c * HW + base + px];
    }
    gate_sync();   // wait for weight transposes (hidden under tile load)

    ull acc[PIX / 2];
#pragma unroll
    for (int v = 0; v < PIX / 2; v++) acc[v] = 0ULL;

    const float* wcol = WkT + tid;   // lanes consecutive -> coalesced
#pragma unroll 8
    for (int c = 0; c < C; c++) {
        ull ww = bcast2(__ldg(wcol + c * 128));
        const double2* s2 = reinterpret_cast<const double2*>(&s[c * PIX]);
#pragma unroll
        for (int v = 0; v < PIX / 4; v++) {
            double2 d = s2[v];
            ffma2(acc[2 * v],     ww, d2u(d.x));
            ffma2(acc[2 * v + 1], ww, d2u(d.y));
        }
    }
#pragma unroll
    for (int v = 0; v < PIX / 2; v++) {
        out[(base + 2 * v) * 128 + tid]     = __float2half_rn(lo2(acc[v]));
        out[(base + 2 * v + 1) * 128 + tid] = __float2half_rn(hi2(acc[v]));
    }
}

#define LOC_STRIDE 20   // padded q-stride: multiple of 4 -> 16B-aligned double2
#define LOC_REF    (128 * LOC_STRIDE)
__device__ void loc_block(int b,
                          const float* __restrict__ query,
                          const float* __restrict__ refp,
                          const float* __restrict__ boff,
                          float* s /* >= 2656 floats */) {
    const int qb = b * 16;
    const int tid = threadIdx.x;
    // s[0 .. 128*20): q tile [c][16 (pad 20)] ; s[2560 .. 2656): ref [16][6]
    for (int i = tid; i < 16 * 128; i += 128) {
        int q = i >> 7, c = i & 127;
        s[c * LOC_STRIDE + q] = query[(qb + q) * 128 + c];
    }
    if (tid < 96) s[LOC_REF + tid] = refp[qb * 6 + tid];
    gate_sync();   // wait for Woff transpose (hidden under tile load)

#pragma unroll
    for (int k = 0; k < 3; k++) {
        const int t = k * 128 + tid;      // 0..383
        const int j = t % 192;
        const int qh = t / 192;
        const int xy = j & 1;
        const int l = (j >> 3) % 3;
        const float scale = 1.f / (float)(128 >> l);

        ull acc[4] = {0, 0, 0, 0};
        const float* wcol = g_wofft + j;
#pragma unroll 8
        for (int c = 0; c < 128; c++) {
            ull w = bcast2(__ldg(wcol + c * 192));
            const double2* s2 =
                reinterpret_cast<const double2*>(&s[c * LOC_STRIDE + qh * 8]);
            double2 dA = s2[0], dB = s2[1];
            ffma2(acc[0], w, d2u(dA.x));
            ffma2(acc[1], w, d2u(dA.y));
            ffma2(acc[2], w, d2u(dB.x));
            ffma2(acc[3], w, d2u(dB.y));
        }
        const float bo = __ldg(boff + j);
#pragma unroll
        for (int v = 0; v < 4; v++) {
            const int q0 = qh * 8 + 2 * v, q1 = q0 + 1;
            const float r0 = s[LOC_REF + q0 * 6 + l * 2 + xy];
            const float r1 = s[LOC_REF + q1 * 6 + l * 2 + xy];
            g_loc[(qb + q0) * 192 + j] = r0 + (lo2(acc[v]) + bo) * scale;
            g_loc[(qb + q1) * 192 + j] = r1 + (hi2(acc[v]) + bo) * scale;
        }
    }
}

// prep: 64 producers (weight transposes) + 16 WoutT + 1 LUT
//       + 400 loc + 512 p0 + 128 p1 + 32 p2   = 1153 blocks
__global__ __launch_bounds__(128)
void prep_kernel(const float* __restrict__ feat0,
                 const float* __restrict__ feat1,
                 const float* __restrict__ feat2,
                 const float* __restrict__ query,
                 const float* __restrict__ refp,
                 const float* __restrict__ boff,
                 const float* __restrict__ Woff,
                 const float* __restrict__ Wout,
                 const float* __restrict__ Wk0,
                 const float* __restrict__ Wk1,
                 const float* __restrict__ Wk2) {
    __shared__ float s[128 * 32];
    const int b = blockIdx.x;
    if (b < N_PRODUCERS) {
        // producers: transposes consumed by this same launch
        if (b < 24)      transpose_tile(Woff, g_wofft, 192, 128, b, s);
        else if (b < 40) transpose_tile(Wk0,  g_wk0t,  128, 128, b - 24, s);
        else if (b < 56) transpose_tile(Wk1,  g_wk1t,  128, 128, b - 40, s);
        else             transpose_tile(Wk2,  g_wk2t,  128, 64,  b - 56, s);
        __threadfence();
        __syncthreads();
        if (threadIdx.x == 0) atomicAdd(&g_gate, 1);
    } else if (b < 80) {
        // Wout transpose: consumed only by main (next launch) — no gate
        transpose_tile(Wout, g_woutt, 128, 128, b - 64, s);
    } else if (b == 80) {
        const int t = threadIdx.x;
        if (t < 96) {
            int h = t / 12, lp = t % 12, l = lp >> 2;
            const __half* base = (l == 0) ? g_proj0 : (l == 1) ? g_proj1 : g_proj2;
            ull p = (ull)(base + h * D_HEAD);
            int Wl = 128 >> l;
            g_lut[t] = make_uint4((unsigned)p, (unsigned)(p >> 32),
                                  (unsigned)(Wl | (Wl << 16)), (unsigned)(h * 3 + l));
        }
    } else if (b < 481) {
        loc_block(b - 81, query, refp, boff, s);
    } else if (b < 993) {
        proj_block<128>(feat0, g_wk0t, g_proj0, HW0, b - 481, s);
    } else if (b < 1121) {
        proj_block<128>(feat1, g_wk1t, g_proj1, HW1, b - 993, s);
    } else {
        proj_block<64>(feat2, g_wk2t, g_proj2, HW2, b - 1121, s);
    }
}
#define PREP_BLOCKS 1153

// ---------------------------------------------------------------------------
// Fused attention kernel. QB=4 queries / block, 256 threads. Includes output
// projection (phase F) — WoutT reads hide under gather latency slack.
// ---------------------------------------------------------------------------
#define QB 4
#define THREADS 256
#define NSAMP (N_HEADS * N_LEVELS * N_POINTS)   // 96
#define LPP   (N_LEVELS * N_POINTS)             // 12
#define HT_STRIDE 6   // 128*6 = 768 = LOC size; even -> ull-aligned; 2-way banks

#define SM_QS    0
#define SM_LOC   (SM_QS + QB*128)            // 512
#define SM_HT    SM_LOC                      // alias (LOC dead after C) 768
#define SM_KS    (SM_LOC + QB*192)           // 1280
#define SM_PF    SM_KS                       // alias (KS dead after E) 512
#define SM_LG    (SM_KS + QB*NSAMP*16)       // 7424
#define SM_QBK   (SM_LG + QB*NSAMP)          // 7808
#define SM_TOTAL (SM_QBK + QB*24)            // 7904
#define SMEM_BYTES (SM_TOTAL * sizeof(float))

__global__ __launch_bounds__(THREADS)
void msda_main_kernel(const float* __restrict__ query,
                      const float* __restrict__ bk0,
                      const float* __restrict__ bk1,
                      const float* __restrict__ bk2,
                      const float* __restrict__ WoutT,
                      const float* __restrict__ bout,
                      float* __restrict__ out) {
    extern __shared__ float sm[];
    const int tid = threadIdx.x;
    const int qbase = blockIdx.x * QB;

    // reset the prep gate for the next graph replay (main is stream-ordered
    // after prep; next replay's prep is stream-ordered after this kernel)
    if (blockIdx.x == 0 && tid == 0) g_gate = 0;

    // ---- Phase A: vectorized loads ------------------------------------------
    {
        const float4* qsrc = reinterpret_cast<const float4*>(query + qbase * 128);
        const float4* lsrc = reinterpret_cast<const float4*>(g_loc + qbase * 192);
        float4* qdst = reinterpret_cast<float4*>(&sm[SM_QS]);
        float4* ldst = reinterpret_cast<float4*>(&sm[SM_LOC]);
        for (int i = tid; i < 320; i += THREADS) {
            if (i < 128) qdst[i] = qsrc[i];
            else         ldst[i - 128] = lsrc[i - 128];
        }
    }
    __syncthreads();

    // ---- Phase A2: qbk[q][h][l] = q_h . bk_l_h -------------------------------
    if (tid < QB * 24) {
        const int q = tid / 24;
        const int r = tid % 24;
        const int h = r / 3;
        const int l = r % 3;
        const float* bk = (l == 0) ? bk0 : (l == 1) ? bk1 : bk2;
        const float* qp = &sm[SM_QS + q * 128 + h * D_HEAD];
        float a = 0.f;
#pragma unroll
        for (int d = 0; d < D_HEAD; d++)
            a += qp[d] * __ldg(bk + h * D_HEAD + d);
        sm[SM_QBK + tid] = a;
    }
    __syncthreads();

    // ---- Phase C: quad-cooperative bilinear gather (fp16 feats) + logits -----
#pragma unroll
    for (int it = 0; it < 6; it++) {
        const int i = it * THREADS + tid;
        const int q = i / 384;
        const int r = i - q * 384;
        const int s = r >> 2;
        const int d4 = r & 3;

        const uint4 e = __ldg(&g_lut[s]);
        const __half* projc = (const __half*)(((ull)e.y << 32) | (ull)e.x);
        const int Wl = (int)(e.z & 0xffffu);
        const int Hl = (int)(e.z >> 16);

        const float locx = sm[SM_LOC + q * 192 + s * 2];
        const float locy = sm[SM_LOC + q * 192 + s * 2 + 1];

        const float x = locx * (float)Wl - 0.5f;
        const float y = locy * (float)Hl - 0.5f;
        const float xf = floorf(x), yf = floorf(y);
        const int x0 = (int)xf, y0 = (int)yf;
        const float wx = x - xf, wy = y - yf;

        float wgt[4];
        const uint2* addr[4];
#pragma unroll
        for (int t = 0; t < 4; t++) {
            const int xi = x0 + (t & 1);
            const int yi = y0 + (t >> 1);
            const bool valid = (xi >= 0) & (xi < Wl) & (yi >= 0) & (yi < Hl);
            const float w = ((t & 1) ? wx : (1.f - wx)) * ((t >> 1) ? wy : (1.f - wy));
            wgt[t] = valid ? w : 0.f;
            const int xic = min(max(xi, 0), Wl - 1);
            const int yic = min(max(yi, 0), Hl - 1);
            addr[t] = reinterpret_cast<const uint2*>(projc + (yic * Wl + xic) * 128) + d4;
        }
        uint2 u0 = __ldg(addr[0]);
        uint2 u1 = __ldg(addr[1]);
        uint2 u2 = __ldg(addr[2]);
        uint2 u3 = __ldg(addr[3]);

        float2 a0 = __half22float2(*reinterpret_cast<__half2*>(&u0.x));
        float2 b0 = __half22float2(*reinterpret_cast<__half2*>(&u0.y));
        float2 a1 = __half22float2(*reinterpret_cast<__half2*>(&u1.x));
        float2 b1 = __half22float2(*reinterpret_cast<__half2*>(&u1.y));
        float2 a2 = __half22float2(*reinterpret_cast<__half2*>(&u2.x));
        float2 b2 = __half22float2(*reinterpret_cast<__half2*>(&u2.y));
        float2 a3 = __half22float2(*reinterpret_cast<__half2*>(&u3.x));
        float2 b3 = __half22float2(*reinterpret_cast<__half2*>(&u3.y));

        float4 k;
        k.x = wgt[0] * a0.x + wgt[1] * a1.x + wgt[2] * a2.x + wgt[3] * a3.x;
        k.y = wgt[0] * a0.y + wgt[1] * a1.y + wgt[2] * a2.y + wgt[3] * a3.y;
        k.z = wgt[0] * b0.x + wgt[1] * b1.x + wgt[2] * b2.x + wgt[3] * b3.x;
        k.w = wgt[0] * b0.y + wgt[1] * b1.y + wgt[2] * b2.y + wgt[3] * b3.y;

        const int coff = (s / LPP) * D_HEAD + d4 * 4;
        const float4 qv = *reinterpret_cast<const float4*>(&sm[SM_QS + q * 128 + coff]);
        float part = qv.x * k.x + qv.y * k.y + qv.z * k.z + qv.w * k.w;
        part += __shfl_xor_sync(0xffffffffu, part, 1);
        part += __shfl_xor_sync(0xffffffffu, part, 2);

        *reinterpret_cast<float4*>(&sm[SM_KS + (q * NSAMP + s) * D_HEAD + d4 * 4]) = k;
        if (d4 == 0)
            sm[SM_LG + q * NSAMP + s] = part + sm[SM_QBK + q * 24 + e.w];
    }
    __syncthreads();

    // ---- Phase D: softmax per (q, h) over 12 ---------------------------------
    if (tid < QB * N_HEADS) {
        const int q = tid / N_HEADS, h = tid % N_HEADS;
        float* lrow = &sm[SM_LG + q * NSAMP + h * LPP];
        float m = -1e30f;
#pragma unroll
        for (int t = 0; t < LPP; t++) m = fmaxf(m, 0.25f * lrow[t]);
        float ssum = 0.f;
#pragma unroll
        for (int t = 0; t < LPP; t++) {
            float e = __expf(0.25f * lrow[t] - m);
            lrow[t] = e;
            ssum += e;
        }
        float inv = 1.f / ssum;
#pragma unroll
        for (int t = 0; t < LPP; t++) lrow[t] *= inv;
    }
    __syncthreads();

    // ---- Phase E: weighted sum (+ bias via attn level-sums) -> HT [c][q] -----
#pragma unroll
    for (int it = 0; it < 2; it++) {
        const int i = it * THREADS + tid;
        const int q = i >> 7;
        const int hd = i & 127;
        const int h = hd >> 4;
        const int d = hd & 15;
        const float* attn = &sm[SM_LG + q * NSAMP + h * LPP];
        const float* kk = &sm[SM_KS + (q * NSAMP + h * LPP) * D_HEAD + d];
        float a = 0.f;
        float w0 = 0.f, w1 = 0.f, w2 = 0.f;
#pragma unroll
        for (int lp = 0; lp < LPP; lp++) {
            const float at = attn[lp];
            a += at * kk[lp * D_HEAD];
            if (lp < 4) w0 += at;
            else if (lp < 8) w1 += at;
            else w2 += at;
        }
        a += w0 * __ldg(bk0 + hd) + w1 * __ldg(bk1 + hd) + w2 * __ldg(bk2 + hd);
        sm[SM_HT + hd * HT_STRIDE + q] = a;
    }
    __syncthreads();

    // ---- Phase F: out[q][o] = hs[q] . WoutT[:,o] + b, c-split over 2 halves --
    {
        const int o = tid & 127;
        const int chalf = tid >> 7;
        const int cbase = chalf * 64;
        ull acc[2] = {0, 0};
        const float* wt = WoutT + o;
#pragma unroll 4
        for (int c = 0; c < 64; c++) {
            const int cc = cbase + c;
            ull ww = bcast2(__ldg(wt + cc * 128));
            const ull* hp = reinterpret_cast<const ull*>(&sm[SM_HT + cc * HT_STRIDE]);
            ffma2(acc[0], ww, hp[0]);
            ffma2(acc[1], ww, hp[1]);
        }
        if (chalf == 1) {
            ull* pf = reinterpret_cast<ull*>(&sm[SM_PF]);
            pf[o * 2]     = acc[0];
            pf[o * 2 + 1] = acc[1];
        }
        __syncthreads();
        if (chalf == 0) {
            const float* pf = &sm[SM_PF + o * 4];
            const float b = __ldg(bout + o);
            out[(qbase + 0) * 128 + o] = lo2(acc[0]) + pf[0] + b;
            out[(qbase + 1) * 128 + o] = hi2(acc[0]) + pf[1] + b;
            out[(qbase + 2) * 128 + o] = lo2(acc[1]) + pf[2] + b;
            out[(qbase + 3) * 128 + o] = hi2(acc[1]) + pf[3] + b;
        }
    }
}

// ---------------------------------------------------------------------------
// Launch
// ---------------------------------------------------------------------------
extern "C" void kernel_launch(void* const* d_in, const int* in_sizes, int n_in,
                              void* d_out, int out_size) {
    const float* query = (const float*)d_in[0];
    const float* refp  = (const float*)d_in[1];
    const float* feat0 = (const float*)d_in[2];
    const float* feat1 = (const float*)d_in[3];
    const float* feat2 = (const float*)d_in[4];
    const float* Woff  = (const float*)d_in[6];
    const float* boff  = (const float*)d_in[7];
    const float* Wk0   = (const float*)d_in[8];
    const float* bk0   = (const float*)d_in[9];
    const float* Wk1   = (const float*)d_in[10];
    const float* bk1   = (const float*)d_in[11];
    const float* Wk2   = (const float*)d_in[12];
    const float* bk2   = (const float*)d_in[13];
    const float* Wout  = (const float*)d_in[14];
    const float* bout  = (const float*)d_in[15];
    float* out = (float*)d_out;

    float* woutt;
    cudaGetSymbolAddress((void**)&woutt, g_woutt);

    static bool attr_set = false;
    if (!attr_set) {
        cudaFuncSetAttribute(msda_main_kernel,
                             cudaFuncAttributeMaxDynamicSharedMemorySize,
                             (int)SMEM_BYTES);
        cudaFuncSetAttribute(prep_kernel,
                             cudaFuncAttributePreferredSharedMemoryCarveout, 50);
        attr_set = true;
    }

    prep_kernel<<<PREP_BLOCKS, 128>>>(feat0, feat1, feat2, query, refp, boff,
                                      Woff, Wout, Wk0, Wk1, Wk2);
    msda_main_kernel<<<LQ / QB, THREADS, SMEM_BYTES>>>(
        query, bk0, bk1, bk2, woutt, bout, out);
}